// round 16
// baseline (speedup 1.0000x reference)
#include <cuda_runtime.h>
#include <cuda_bf16.h>
#include <cuda_fp16.h>
#include <math.h>
#include <stdint.h>

// ---------------------------------------------------------------------------
// Problem constants (B=2, S=2048, D_MODEL=1024, H=16, Dh=64)
// ---------------------------------------------------------------------------
#define NB      2
#define SEQ     2048
#define DM      1024
#define NHEADS  16
#define HEAD    64

__device__ float g_bias[NHEADS * 4096];

// bf16 split operands for projection GEMMs
__device__ __nv_bfloat16 g_Ahi[3][4096 * 1024];
__device__ __nv_bfloat16 g_Alo[3][4096 * 1024];
__device__ __nv_bfloat16 g_Bhi[3][1024 * 1024];
__device__ __nv_bfloat16 g_Blo[3][1024 * 1024];

// Q/K split outputs (bf16 hi/lo); V output as SINGLE fp16
#define QKV_ELE (NB * NHEADS * SEQ * HEAD)
__device__ __nv_bfloat16 g_qhi[QKV_ELE], g_qlo[QKV_ELE];
__device__ __nv_bfloat16 g_khi[QKV_ELE], g_klo[QKV_ELE];
__device__ __half        g_vh [QKV_ELE];

// ---------------------------------------------------------------------------
// PTX helpers
// ---------------------------------------------------------------------------
__device__ __forceinline__ uint32_t smem_u32(const void* p) {
    uint32_t a;
    asm("{ .reg .u64 t; cvta.to.shared.u64 t, %1; cvt.u32.u64 %0, t; }"
        : "=r"(a) : "l"(p));
    return a;
}
#define CP_ASYNC16(dst, src) \
    asm volatile("cp.async.cg.shared.global [%0], [%1], 16;" :: "r"(dst), "l"(src))
#define CP_COMMIT() asm volatile("cp.async.commit_group;" ::: "memory")
#define CP_WAIT(n)  asm volatile("cp.async.wait_group %0;" :: "n"(n) : "memory")

#define LDMATRIX_X4(r0, r1, r2, r3, addr) \
    asm volatile("ldmatrix.sync.aligned.m8n8.x4.shared.b16 {%0,%1,%2,%3}, [%4];" \
                 : "=r"(r0), "=r"(r1), "=r"(r2), "=r"(r3) : "r"(addr))
#define LDMATRIX_X4T(r0, r1, r2, r3, addr) \
    asm volatile("ldmatrix.sync.aligned.m8n8.x4.trans.shared.b16 {%0,%1,%2,%3}, [%4];" \
                 : "=r"(r0), "=r"(r1), "=r"(r2), "=r"(r3) : "r"(addr))

__device__ __forceinline__ void mma_bf16(float* d, const uint32_t* a,
                                         const uint32_t* b) {
    asm volatile(
        "mma.sync.aligned.m16n8k16.row.col.f32.bf16.bf16.f32 "
        "{%0,%1,%2,%3}, {%4,%5,%6,%7}, {%8,%9}, {%0,%1,%2,%3};"
        : "+f"(d[0]), "+f"(d[1]), "+f"(d[2]), "+f"(d[3])
        : "r"(a[0]), "r"(a[1]), "r"(a[2]), "r"(a[3]), "r"(b[0]), "r"(b[1]));
}
__device__ __forceinline__ void mma_fp16(float* d, const uint32_t* a,
                                         const uint32_t* b) {
    asm volatile(
        "mma.sync.aligned.m16n8k16.row.col.f32.f16.f16.f32 "
        "{%0,%1,%2,%3}, {%4,%5,%6,%7}, {%8,%9}, {%0,%1,%2,%3};"
        : "+f"(d[0]), "+f"(d[1]), "+f"(d[2]), "+f"(d[3])
        : "r"(a[0]), "r"(a[1]), "r"(a[2]), "r"(a[3]), "r"(b[0]), "r"(b[1]));
}
__device__ __forceinline__ uint32_t pack_bf2(float a, float b) {
    __nv_bfloat162 t = __floats2bfloat162_rn(a, b);
    return *(uint32_t*)&t;
}
__device__ __forceinline__ uint32_t pack_h2(float a, float b) {
    __half2 t = __floats2half2_rn(a, b);
    return *(uint32_t*)&t;
}

// ---------------------------------------------------------------------------
// Kernel 1: relative-position bias table expansion (known-good)
// ---------------------------------------------------------------------------
__global__ void bias_precompute_kernel(const float* __restrict__ bias_table) {
    int i = blockIdx.x * blockDim.x + threadIdx.x;
    if (i >= 4095) return;
    int delta = i - 2047;
    int ret = (delta > 0) ? 16 : 0;
    int rp = abs(delta);
    int bucket;
    if (rp < 8) {
        bucket = ret + rp;
    } else {
        int vl;
        if ((rp & (rp - 1)) == 0) {
            int k = __ffs(rp) - 1;
            vl = 8 + 2 * (k - 3);
        } else {
            float t = logf((float)rp * 0.125f) / 2.7725887f;
            vl = 8 + (int)(t * 8.0f);
        }
        bucket = ret + min(vl, 15);
    }
    #pragma unroll
    for (int h = 0; h < NHEADS; h++)
        g_bias[h * 4096 + i] = bias_table[bucket * NHEADS + h];
}

// ---------------------------------------------------------------------------
// Kernel 2a: split activations X -> bf16 hi/lo
// ---------------------------------------------------------------------------
__global__ void __launch_bounds__(256) convert_x_kernel(
    const float* __restrict__ Xq, const float* __restrict__ Xk,
    const float* __restrict__ Xv)
{
    int z = blockIdx.y;
    const float* X = (z == 0) ? Xq : (z == 1) ? Xk : Xv;
    __nv_bfloat16* hi = g_Ahi[z];
    __nv_bfloat16* lo = g_Alo[z];
    size_t i = ((size_t)blockIdx.x * 256 + threadIdx.x) * 4;
    float4 v = *(const float4*)(X + i);
    float f[4] = {v.x, v.y, v.z, v.w};
    #pragma unroll
    for (int j = 0; j < 4; j++) {
        __nv_bfloat16 h = __float2bfloat16(f[j]);
        hi[i + j] = h;
        lo[i + j] = __float2bfloat16(f[j] - __bfloat162float(h));
    }
}

// ---------------------------------------------------------------------------
// Kernel 2b: transpose + split weights  W[k][n] -> Wt[n][k] bf16 hi/lo
// ---------------------------------------------------------------------------
__global__ void __launch_bounds__(1024) convert_w_kernel(
    const float* __restrict__ Wq, const float* __restrict__ Wk,
    const float* __restrict__ Wv)
{
    __shared__ float tile[32][33];
    int z = blockIdx.z;
    const float* W = (z == 0) ? Wq : (z == 1) ? Wk : Wv;
    int k0 = blockIdx.x * 32;
    int n0 = blockIdx.y * 32;
    int tx = threadIdx.x, ty = threadIdx.y;
    tile[ty][tx] = W[(size_t)(k0 + ty) * DM + n0 + tx];
    __syncthreads();
    float v = tile[tx][ty];
    __nv_bfloat16 h = __float2bfloat16(v);
    size_t idx = (size_t)(n0 + ty) * DM + k0 + tx;
    g_Bhi[z][idx] = h;
    g_Blo[z][idx] = __float2bfloat16(v - __bfloat162float(h));
}

// ---------------------------------------------------------------------------
// Kernel 3: projection GEMM, FUSED 3-pass split, single barrier per k-iter.
// MMA ISSUE ORDER: all 8 accs get aHi*Bhi, then all 8 get aHi*Blo, then all 8
// get aLo*Bhi -> same-accumulator reuse distance 8 (was 1). Per-accumulator
// contribution order unchanged -> bit-identical results.
// ---------------------------------------------------------------------------
#define BK 32
#define TB 10240
#define STAGE_B (4 * TB)
#define PROJ_SMEM (2 * STAGE_B)          // 81920 B
#define NCHUNK 32

__global__ void __launch_bounds__(256, 2) proj_mma_kernel() {
    extern __shared__ char psm[];

    const int tid  = threadIdx.x;
    const int lane = tid & 31;
    const int wid  = tid >> 5;
    const int wm   = wid >> 2;
    const int wn   = wid & 3;
    const int grp  = lane >> 2;
    const int q4   = lane & 3;

    const int z   = blockIdx.z;
    const int bm0 = blockIdx.y * 128;
    const int bn0 = blockIdx.x * 128;

    const __nv_bfloat16* __restrict__ srcs[4] = {
        g_Ahi[z], g_Alo[z], g_Bhi[z], g_Blo[z] };

    const uint32_t s0 = smem_u32(psm);

    float acc[4][4][4];
    #pragma unroll
    for (int i = 0; i < 4; i++)
        #pragma unroll
        for (int j = 0; j < 4; j++)
            #pragma unroll
            for (int r = 0; r < 4; r++) acc[i][j][r] = 0.0f;

    auto load_chunk = [&](int t, int s) {
        int k0 = t * BK;
        uint32_t base = s0 + s * STAGE_B;
        #pragma unroll
        for (int arr = 0; arr < 4; arr++) {
            int r0 = (arr < 2) ? bm0 : bn0;
            #pragma unroll
            for (int j = 0; j < 2; j++) {
                int id = tid + 256 * j;
                int row = id >> 2, part = id & 3;
                uint32_t off = (uint32_t)(row * 80 + part * 16);
                CP_ASYNC16(base + arr * TB + off,
                           srcs[arr] + (size_t)(r0 + row) * DM + k0 + part * 8);
            }
        }
        CP_COMMIT();
    };

    const int l7  = lane & 7;
    const int l8  = (lane >> 3) & 1;
    const int l16 = (lane >> 4) & 1;

    load_chunk(0, 0);

    for (int t = 0; t < NCHUNK; t++) {
        CP_WAIT(0);
        __syncthreads();                 // publish load t; order prior reads
        if (t + 1 < NCHUNK) load_chunk(t + 1, (t + 1) & 1);

        const int s = t & 1;
        const uint32_t aHi = s0 + s * STAGE_B;
        const uint32_t aLo = aHi + TB;
        const uint32_t bHi = aHi + 2 * TB;
        const uint32_t bLo = aHi + 3 * TB;

        #pragma unroll
        for (int ks = 0; ks < 2; ks++) {
            const int kb = ks * 16;
            uint32_t bhif[4][2], blof[4][2];
            #pragma unroll
            for (int bp = 0; bp < 2; bp++) {
                uint32_t off = (uint32_t)((wn * 32 + bp * 16 + l16 * 8 + l7) * 80 +
                                          (kb + l8 * 8) * 2);
                uint32_t r0, r1, r2, r3;
                LDMATRIX_X4(r0, r1, r2, r3, bHi + off);
                bhif[bp * 2 + 0][0] = r0; bhif[bp * 2 + 0][1] = r1;
                bhif[bp * 2 + 1][0] = r2; bhif[bp * 2 + 1][1] = r3;
                LDMATRIX_X4(r0, r1, r2, r3, bLo + off);
                blof[bp * 2 + 0][0] = r0; blof[bp * 2 + 0][1] = r1;
                blof[bp * 2 + 1][0] = r2; blof[bp * 2 + 1][1] = r3;
            }
            #pragma unroll
            for (int mh = 0; mh < 2; mh++) {
                uint32_t afrag[2][4];
                // A-hi fragments
                #pragma unroll
                for (int mi = 0; mi < 2; mi++) {
                    int mt = mh * 2 + mi;
                    uint32_t addr = aHi +
                        (uint32_t)((wm * 64 + mt * 16 + l8 * 8 + l7) * 80 +
                                   (kb + l16 * 8) * 2);
                    LDMATRIX_X4(afrag[mi][0], afrag[mi][1], afrag[mi][2], afrag[mi][3], addr);
                }
                // pass 1: aHi * Bhi over all 8 accs (distance 8)
                #pragma unroll
                for (int mi = 0; mi < 2; mi++)
                    #pragma unroll
                    for (int nt = 0; nt < 4; nt++)
                        mma_bf16(acc[mh * 2 + mi][nt], afrag[mi], bhif[nt]);
                // pass 2: aHi * Blo over all 8 accs
                #pragma unroll
                for (int mi = 0; mi < 2; mi++)
                    #pragma unroll
                    for (int nt = 0; nt < 4; nt++)
                        mma_bf16(acc[mh * 2 + mi][nt], afrag[mi], blof[nt]);
                // A-lo fragments (reuse regs)
                #pragma unroll
                for (int mi = 0; mi < 2; mi++) {
                    int mt = mh * 2 + mi;
                    uint32_t addr = aLo +
                        (uint32_t)((wm * 64 + mt * 16 + l8 * 8 + l7) * 80 +
                                   (kb + l16 * 8) * 2);
                    LDMATRIX_X4(afrag[mi][0], afrag[mi][1], afrag[mi][2], afrag[mi][3], addr);
                }
                // pass 3: aLo * Bhi over all 8 accs
                #pragma unroll
                for (int mi = 0; mi < 2; mi++)
                    #pragma unroll
                    for (int nt = 0; nt < 4; nt++)
                        mma_bf16(acc[mh * 2 + mi][nt], afrag[mi], bhif[nt]);
            }
        }
    }

    // epilogue
    if (z == 2) {
        #pragma unroll
        for (int mt = 0; mt < 4; mt++) {
            #pragma unroll
            for (int half = 0; half < 2; half++) {
                int m = bm0 + wm * 64 + mt * 16 + grp + half * 8;
                int bb = m >> 11;
                int ss = m & (SEQ - 1);
                #pragma unroll
                for (int nt = 0; nt < 4; nt++) {
                    int n = bn0 + wn * 32 + nt * 8 + q4 * 2;
                    int h = n >> 6, d = n & 63;
                    size_t idx = (((size_t)(bb * NHEADS + h) * SEQ + ss) << 6) + d;
                    *(uint32_t*)&g_vh[idx] =
                        pack_h2(acc[mt][nt][half * 2 + 0], acc[mt][nt][half * 2 + 1]);
                }
            }
        }
    } else {
        __nv_bfloat16* dhi = (z == 0) ? g_qhi : g_khi;
        __nv_bfloat16* dlo = (z == 0) ? g_qlo : g_klo;
        #pragma unroll
        for (int mt = 0; mt < 4; mt++) {
            #pragma unroll
            for (int half = 0; half < 2; half++) {
                int m = bm0 + wm * 64 + mt * 16 + grp + half * 8;
                int bb = m >> 11;
                int ss = m & (SEQ - 1);
                #pragma unroll
                for (int nt = 0; nt < 4; nt++) {
                    int n = bn0 + wn * 32 + nt * 8 + q4 * 2;
                    int h = n >> 6, d = n & 63;
                    float x = acc[mt][nt][half * 2 + 0];
                    float y = acc[mt][nt][half * 2 + 1];
                    float xh = __bfloat162float(__float2bfloat16(x));
                    float yh = __bfloat162float(__float2bfloat16(y));
                    size_t idx = (((size_t)(bb * NHEADS + h) * SEQ + ss) << 6) + d;
                    *(uint32_t*)&dhi[idx] = pack_bf2(x, y);
                    *(uint32_t*)&dlo[idx] = pack_bf2(x - xh, y - yh);
                }
            }
        }
    }
}

// ---------------------------------------------------------------------------
// Kernel 4: flash attention. QK = 3-product bf16 split with REORDERED issue
// (all qhi*Khi over 8 accs, then qlo*Khi, then qhi*Klo -> distance 8);
// PV = single fp16 product (already distance 8).
// ---------------------------------------------------------------------------
#define AT_RB   144
#define AT_TILE (64 * AT_RB)                      // 9216 B per 64x64 tile
#define A2NS    2
#define A2_BW   (A2NS * 3 * AT_TILE)              // 55296
#define A2_MW   (A2_BW + A2NS * 128 * 4)          // 56320
#define A2_SMEM (A2_MW + A2NS * 64 * 4)           // 56832
#define NKT     (SEQ / 64)

__global__ void __launch_bounds__(128, 3) attn_mma_kernel(
    const float* __restrict__ key_mask, float* __restrict__ out)
{
    extern __shared__ char dsm[];
    const uint32_t sb = smem_u32(dsm);

    const int tid  = threadIdx.x;
    const int lane = tid & 31;
    const int wid  = tid >> 5;
    const int g    = lane >> 2;
    const int q4   = lane & 3;
    const int l7   = lane & 7;
    const int l8   = (lane >> 3) & 1;
    const int l16  = (lane >> 4) & 1;

    const int qt0 = blockIdx.x * 64;
    const int h   = blockIdx.y;
    const int b   = blockIdx.z;
    const size_t bh = ((size_t)(b * NHEADS + h)) << 17;

    const __nv_bfloat16* Khi = g_khi + bh;
    const __nv_bfloat16* Klo = g_klo + bh;
    const __nv_bfloat16* Vh  = (const __nv_bfloat16*)(g_vh + bh);  // addr only
    const float* bias_h = g_bias + h * 4096;

    auto issue_kv = [&](int kt, int s) {
        const __nv_bfloat16* srcs[3] = { Khi, Klo, Vh };
        #pragma unroll
        for (int arr = 0; arr < 3; arr++)
            #pragma unroll
            for (int jj = 0; jj < 4; jj++) {
                int rem = jj * 128 + tid;
                int row = rem >> 3, part = rem & 7;
                uint32_t dst = sb + (s * 3 + arr) * AT_TILE + row * AT_RB + part * 16;
                CP_ASYNC16(dst, srcs[arr] + (size_t)(kt * 64 + row) * HEAD + part * 8);
            }
        CP_COMMIT();
        float* bw = (float*)(dsm + A2_BW + s * 512);
        float* mw = (float*)(dsm + A2_MW + s * 256);
        if (tid < 127) {
            int idx = kt * 64 + tid - 63 - qt0 + 2047;
            idx = max(0, min(4094, idx));
            bw[tid] = bias_h[idx];
        }
        if (tid < 64) {
            float mk = key_mask[(size_t)b * SEQ + kt * 64 + tid];
            mw[tid] = (1.0f - mk) * -10000.0f;
        }
    };

    issue_kv(0, 0);

    // ---- Q fragments: direct gmem->register loads in mma A-layout ----
    uint32_t qhi[4][4], qlo[4][4];
    {
        const __nv_bfloat16* Qh = g_qhi + bh;
        const __nv_bfloat16* Ql = g_qlo + bh;
        int r0 = qt0 + wid * 16 + g;
        #pragma unroll
        for (int kk = 0; kk < 4; kk++) {
            int c0 = kk * 16 + q4 * 2;
            qhi[kk][0] = *(const uint32_t*)&Qh[(size_t)(r0)     * HEAD + c0];
            qhi[kk][1] = *(const uint32_t*)&Qh[(size_t)(r0 + 8) * HEAD + c0];
            qhi[kk][2] = *(const uint32_t*)&Qh[(size_t)(r0)     * HEAD + c0 + 8];
            qhi[kk][3] = *(const uint32_t*)&Qh[(size_t)(r0 + 8) * HEAD + c0 + 8];
            qlo[kk][0] = *(const uint32_t*)&Ql[(size_t)(r0)     * HEAD + c0];
            qlo[kk][1] = *(const uint32_t*)&Ql[(size_t)(r0 + 8) * HEAD + c0];
            qlo[kk][2] = *(const uint32_t*)&Ql[(size_t)(r0)     * HEAD + c0 + 8];
            qlo[kk][3] = *(const uint32_t*)&Ql[(size_t)(r0 + 8) * HEAD + c0 + 8];
        }
    }

    float oacc[8][4];
    #pragma unroll
    for (int nt = 0; nt < 8; nt++)
        #pragma unroll
        for (int r = 0; r < 4; r++) oacc[nt][r] = 0.0f;
    float mrow[2] = { -INFINITY, -INFINITY };
    float lrow[2] = { 0.0f, 0.0f };

    for (int t = 0; t < NKT; t++) {
        CP_WAIT(0);
        __syncthreads();                 // publish load t; order prior reads
        if (t + 1 < NKT) issue_kv(t + 1, (t + 1) & 1);

        const int s = t & 1;
        const uint32_t kb_hi = sb + (s * 3 + 0) * AT_TILE;
        const uint32_t kb_lo = sb + (s * 3 + 1) * AT_TILE;
        const uint32_t vb    = sb + (s * 3 + 2) * AT_TILE;
        const float* bw = (const float*)(dsm + A2_BW + s * 512);
        const float* mw = (const float*)(dsm + A2_MW + s * 256);

        // ---- S = Q K^T (3-pass bf16 split, distance-8 issue order) ----
        float sacc[8][4];
        #pragma unroll
        for (int nt = 0; nt < 8; nt++)
            #pragma unroll
            for (int r = 0; r < 4; r++) sacc[nt][r] = 0.0f;

        #pragma unroll
        for (int kk = 0; kk < 4; kk++) {
            uint32_t bhif[8][2], blof[8][2];
            #pragma unroll
            for (int bp = 0; bp < 4; bp++) {
                uint32_t off = (uint32_t)((bp * 16 + l16 * 8 + l7) * AT_RB +
                                          (kk * 16 + l8 * 8) * 2);
                uint32_t r0, r1, r2, r3;
                LDMATRIX_X4(r0, r1, r2, r3, kb_hi + off);
                bhif[bp * 2][0] = r0; bhif[bp * 2][1] = r1;
                bhif[bp * 2 + 1][0] = r2; bhif[bp * 2 + 1][1] = r3;
                LDMATRIX_X4(r0, r1, r2, r3, kb_lo + off);
                blof[bp * 2][0] = r0; blof[bp * 2][1] = r1;
                blof[bp * 2 + 1][0] = r2; blof[bp * 2 + 1][1] = r3;
            }
            #pragma unroll
            for (int nt = 0; nt < 8; nt++)
                mma_bf16(sacc[nt], qhi[kk], bhif[nt]);
            #pragma unroll
            for (int nt = 0; nt < 8; nt++)
                mma_bf16(sacc[nt], qlo[kk], bhif[nt]);
            #pragma unroll
            for (int nt = 0; nt < 8; nt++)
                mma_bf16(sacc[nt], qhi[kk], blof[nt]);
        }

        // ---- softmax in registers ----
        #pragma unroll
        for (int hl = 0; hl < 2; hl++) {
            int rr = wid * 16 + g + hl * 8;
            float mx = -INFINITY;
            #pragma unroll
            for (int nt = 0; nt < 8; nt++) {
                #pragma unroll
                for (int e = 0; e < 2; e++) {
                    int c = nt * 8 + q4 * 2 + e;
                    float v = sacc[nt][hl * 2 + e] + bw[c - rr + 63] + mw[c];
                    sacc[nt][hl * 2 + e] = v;
                    mx = fmaxf(mx, v);
                }
            }
            mx = fmaxf(mx, __shfl_xor_sync(0xffffffffu, mx, 1));
            mx = fmaxf(mx, __shfl_xor_sync(0xffffffffu, mx, 2));
            float mnew = fmaxf(mrow[hl], mx);
            float corr = __expf(mrow[hl] - mnew);
            mrow[hl] = mnew;
            float sum = 0.0f;
            #pragma unroll
            for (int nt = 0; nt < 8; nt++) {
                #pragma unroll
                for (int e = 0; e < 2; e++) {
                    float p = __expf(sacc[nt][hl * 2 + e] - mnew);
                    sacc[nt][hl * 2 + e] = p;
                    sum += p;
                }
            }
            sum += __shfl_xor_sync(0xffffffffu, sum, 1);
            sum += __shfl_xor_sync(0xffffffffu, sum, 2);
            lrow[hl] = lrow[hl] * corr + sum;
            #pragma unroll
            for (int nt = 0; nt < 8; nt++) {
                oacc[nt][hl * 2 + 0] *= corr;
                oacc[nt][hl * 2 + 1] *= corr;
            }
        }

        // ---- P -> fp16 A-fragments ----
        uint32_t ph[4][4];
        #pragma unroll
        for (int kk = 0; kk < 4; kk++) {
            #pragma unroll
            for (int part = 0; part < 4; part++) {
                int nt = 2 * kk + (part >> 1);
                int o = (part & 1) * 2;
                ph[kk][part] = pack_h2(sacc[nt][o], sacc[nt][o + 1]);
            }
        }

        // ---- O += P V (fp16 single product), V via trans ldmatrix ----
        #pragma unroll
        for (int kk = 0; kk < 4; kk++) {
            uint32_t vhf[8][2];
            #pragma unroll
            for (int db = 0; db < 4; db++) {
                uint32_t off = (uint32_t)((kk * 16 + l8 * 8 + l7) * AT_RB +
                                          (db * 16 + l16 * 8) * 2);
                uint32_t r0, r1, r2, r3;
                LDMATRIX_X4T(r0, r1, r2, r3, vb + off);
                vhf[db * 2][0] = r0; vhf[db * 2][1] = r1;
                vhf[db * 2 + 1][0] = r2; vhf[db * 2 + 1][1] = r3;
            }
            #pragma unroll
            for (int nt = 0; nt < 8; nt++)
                mma_fp16(oacc[nt], ph[kk], vhf[nt]);
        }
    }

    // ---- epilogue: out[b][qrow][h*64 + d] = O / l ----
    #pragma unroll
    for (int hl = 0; hl < 2; hl++) {
        int rr = wid * 16 + g + hl * 8;
        float inv = 1.0f / lrow[hl];
        size_t base = ((size_t)(b * SEQ + qt0 + rr)) * (NHEADS * HEAD) + h * HEAD;
        #pragma unroll
        for (int nt = 0; nt < 8; nt++) {
            int c = nt * 8 + q4 * 2;
            float2 v;
            v.x = oacc[nt][hl * 2 + 0] * inv;
            v.y = oacc[nt][hl * 2 + 1] * inv;
            *(float2*)&out[base + c] = v;
        }
    }
}

// ---------------------------------------------------------------------------
// Launch
// ---------------------------------------------------------------------------
extern "C" void kernel_launch(void* const* d_in, const int* in_sizes, int n_in,
                              void* d_out, int out_size) {
    const float* query    = (const float*)d_in[0];
    const float* key      = (const float*)d_in[1];
    const float* value    = (const float*)d_in[2];
    const float* key_mask = (const float*)d_in[3];
    const float* Wq       = (const float*)d_in[4];
    const float* Wk       = (const float*)d_in[5];
    const float* Wv       = (const float*)d_in[6];
    const float* bias_tab = (const float*)d_in[7];
    float* out = (float*)d_out;

    cudaFuncSetAttribute(proj_mma_kernel,
                         cudaFuncAttributeMaxDynamicSharedMemorySize, PROJ_SMEM);
    cudaFuncSetAttribute(attn_mma_kernel,
                         cudaFuncAttributeMaxDynamicSharedMemorySize, A2_SMEM);

    bias_precompute_kernel<<<16, 256>>>(bias_tab);
    convert_x_kernel<<<dim3(4096, 3), 256>>>(query, key, value);
    convert_w_kernel<<<dim3(32, 32, 3), dim3(32, 32)>>>(Wq, Wk, Wv);
    proj_mma_kernel<<<dim3(8, 32, 3), 256, PROJ_SMEM>>>();
    attn_mma_kernel<<<dim3(SEQ / 64, NHEADS, NB), 128, A2_SMEM>>>(key_mask, out);
}

// round 17
// speedup vs baseline: 1.0307x; 1.0307x over previous
#include <cuda_runtime.h>
#include <cuda_bf16.h>
#include <cuda_fp16.h>
#include <math.h>
#include <stdint.h>

// ---------------------------------------------------------------------------
// Problem constants (B=2, S=2048, D_MODEL=1024, H=16, Dh=64)
// ---------------------------------------------------------------------------
#define NB      2
#define SEQ     2048
#define DM      1024
#define NHEADS  16
#define HEAD    64

__device__ float g_bias[NHEADS * 4096];

// bf16 split operands for projection GEMMs
__device__ __nv_bfloat16 g_Ahi[3][4096 * 1024];
__device__ __nv_bfloat16 g_Alo[3][4096 * 1024];
__device__ __nv_bfloat16 g_Bhi[3][1024 * 1024];
__device__ __nv_bfloat16 g_Blo[3][1024 * 1024];

// Q/K split outputs (bf16 hi/lo); V output as SINGLE fp16
#define QKV_ELE (NB * NHEADS * SEQ * HEAD)
__device__ __nv_bfloat16 g_qhi[QKV_ELE], g_qlo[QKV_ELE];
__device__ __nv_bfloat16 g_khi[QKV_ELE], g_klo[QKV_ELE];
__device__ __half        g_vh [QKV_ELE];

// ---------------------------------------------------------------------------
// PTX helpers
// ---------------------------------------------------------------------------
__device__ __forceinline__ uint32_t smem_u32(const void* p) {
    uint32_t a;
    asm("{ .reg .u64 t; cvta.to.shared.u64 t, %1; cvt.u32.u64 %0, t; }"
        : "=r"(a) : "l"(p));
    return a;
}
#define CP_ASYNC16(dst, src) \
    asm volatile("cp.async.cg.shared.global [%0], [%1], 16;" :: "r"(dst), "l"(src))
#define CP_COMMIT() asm volatile("cp.async.commit_group;" ::: "memory")
#define CP_WAIT(n)  asm volatile("cp.async.wait_group %0;" :: "n"(n) : "memory")

#define LDMATRIX_X4(r0, r1, r2, r3, addr) \
    asm volatile("ldmatrix.sync.aligned.m8n8.x4.shared.b16 {%0,%1,%2,%3}, [%4];" \
                 : "=r"(r0), "=r"(r1), "=r"(r2), "=r"(r3) : "r"(addr))
#define LDMATRIX_X4T(r0, r1, r2, r3, addr) \
    asm volatile("ldmatrix.sync.aligned.m8n8.x4.trans.shared.b16 {%0,%1,%2,%3}, [%4];" \
                 : "=r"(r0), "=r"(r1), "=r"(r2), "=r"(r3) : "r"(addr))

__device__ __forceinline__ void mma_bf16(float* d, const uint32_t* a,
                                         const uint32_t* b) {
    asm volatile(
        "mma.sync.aligned.m16n8k16.row.col.f32.bf16.bf16.f32 "
        "{%0,%1,%2,%3}, {%4,%5,%6,%7}, {%8,%9}, {%0,%1,%2,%3};"
        : "+f"(d[0]), "+f"(d[1]), "+f"(d[2]), "+f"(d[3])
        : "r"(a[0]), "r"(a[1]), "r"(a[2]), "r"(a[3]), "r"(b[0]), "r"(b[1]));
}
__device__ __forceinline__ void mma_fp16(float* d, const uint32_t* a,
                                         const uint32_t* b) {
    asm volatile(
        "mma.sync.aligned.m16n8k16.row.col.f32.f16.f16.f32 "
        "{%0,%1,%2,%3}, {%4,%5,%6,%7}, {%8,%9}, {%0,%1,%2,%3};"
        : "+f"(d[0]), "+f"(d[1]), "+f"(d[2]), "+f"(d[3])
        : "r"(a[0]), "r"(a[1]), "r"(a[2]), "r"(a[3]), "r"(b[0]), "r"(b[1]));
}
__device__ __forceinline__ uint32_t pack_bf2(float a, float b) {
    __nv_bfloat162 t = __floats2bfloat162_rn(a, b);
    return *(uint32_t*)&t;
}
__device__ __forceinline__ uint32_t pack_h2(float a, float b) {
    __half2 t = __floats2half2_rn(a, b);
    return *(uint32_t*)&t;
}

// ---------------------------------------------------------------------------
// Kernel 1: relative-position bias table expansion (known-good)
// ---------------------------------------------------------------------------
__global__ void bias_precompute_kernel(const float* __restrict__ bias_table) {
    int i = blockIdx.x * blockDim.x + threadIdx.x;
    if (i >= 4095) return;
    int delta = i - 2047;
    int ret = (delta > 0) ? 16 : 0;
    int rp = abs(delta);
    int bucket;
    if (rp < 8) {
        bucket = ret + rp;
    } else {
        int vl;
        if ((rp & (rp - 1)) == 0) {
            int k = __ffs(rp) - 1;
            vl = 8 + 2 * (k - 3);
        } else {
            float t = logf((float)rp * 0.125f) / 2.7725887f;
            vl = 8 + (int)(t * 8.0f);
        }
        bucket = ret + min(vl, 15);
    }
    #pragma unroll
    for (int h = 0; h < NHEADS; h++)
        g_bias[h * 4096 + i] = bias_table[bucket * NHEADS + h];
}

// ---------------------------------------------------------------------------
// Kernel 2a: split activations X -> bf16 hi/lo
// ---------------------------------------------------------------------------
__global__ void __launch_bounds__(256) convert_x_kernel(
    const float* __restrict__ Xq, const float* __restrict__ Xk,
    const float* __restrict__ Xv)
{
    int z = blockIdx.y;
    const float* X = (z == 0) ? Xq : (z == 1) ? Xk : Xv;
    __nv_bfloat16* hi = g_Ahi[z];
    __nv_bfloat16* lo = g_Alo[z];
    size_t i = ((size_t)blockIdx.x * 256 + threadIdx.x) * 4;
    float4 v = *(const float4*)(X + i);
    float f[4] = {v.x, v.y, v.z, v.w};
    #pragma unroll
    for (int j = 0; j < 4; j++) {
        __nv_bfloat16 h = __float2bfloat16(f[j]);
        hi[i + j] = h;
        lo[i + j] = __float2bfloat16(f[j] - __bfloat162float(h));
    }
}

// ---------------------------------------------------------------------------
// Kernel 2b: transpose + split weights  W[k][n] -> Wt[n][k] bf16 hi/lo
// ---------------------------------------------------------------------------
__global__ void __launch_bounds__(1024) convert_w_kernel(
    const float* __restrict__ Wq, const float* __restrict__ Wk,
    const float* __restrict__ Wv)
{
    __shared__ float tile[32][33];
    int z = blockIdx.z;
    const float* W = (z == 0) ? Wq : (z == 1) ? Wk : Wv;
    int k0 = blockIdx.x * 32;
    int n0 = blockIdx.y * 32;
    int tx = threadIdx.x, ty = threadIdx.y;
    tile[ty][tx] = W[(size_t)(k0 + ty) * DM + n0 + tx];
    __syncthreads();
    float v = tile[tx][ty];
    __nv_bfloat16 h = __float2bfloat16(v);
    size_t idx = (size_t)(n0 + ty) * DM + k0 + tx;
    g_Bhi[z][idx] = h;
    g_Blo[z][idx] = __float2bfloat16(v - __bfloat162float(h));
}

// ---------------------------------------------------------------------------
// Kernel 3: projection GEMM, FUSED 3-pass split, single barrier per k-iter.
// MMA ISSUE ORDER: all 8 accs get aHi*Bhi, then all 8 get aHi*Blo, then all 8
// get aLo*Bhi -> same-accumulator reuse distance 8 (was 1). Per-accumulator
// contribution order unchanged -> bit-identical results.
// ---------------------------------------------------------------------------
#define BK 32
#define TB 10240
#define STAGE_B (4 * TB)
#define PROJ_SMEM (2 * STAGE_B)          // 81920 B
#define NCHUNK 32

__global__ void __launch_bounds__(256, 2) proj_mma_kernel() {
    extern __shared__ char psm[];

    const int tid  = threadIdx.x;
    const int lane = tid & 31;
    const int wid  = tid >> 5;
    const int wm   = wid >> 2;
    const int wn   = wid & 3;
    const int grp  = lane >> 2;
    const int q4   = lane & 3;

    const int z   = blockIdx.z;
    const int bm0 = blockIdx.y * 128;
    const int bn0 = blockIdx.x * 128;

    const __nv_bfloat16* __restrict__ srcs[4] = {
        g_Ahi[z], g_Alo[z], g_Bhi[z], g_Blo[z] };

    const uint32_t s0 = smem_u32(psm);

    float acc[4][4][4];
    #pragma unroll
    for (int i = 0; i < 4; i++)
        #pragma unroll
        for (int j = 0; j < 4; j++)
            #pragma unroll
            for (int r = 0; r < 4; r++) acc[i][j][r] = 0.0f;

    auto load_chunk = [&](int t, int s) {
        int k0 = t * BK;
        uint32_t base = s0 + s * STAGE_B;
        #pragma unroll
        for (int arr = 0; arr < 4; arr++) {
            int r0 = (arr < 2) ? bm0 : bn0;
            #pragma unroll
            for (int j = 0; j < 2; j++) {
                int id = tid + 256 * j;
                int row = id >> 2, part = id & 3;
                uint32_t off = (uint32_t)(row * 80 + part * 16);
                CP_ASYNC16(base + arr * TB + off,
                           srcs[arr] + (size_t)(r0 + row) * DM + k0 + part * 8);
            }
        }
        CP_COMMIT();
    };

    const int l7  = lane & 7;
    const int l8  = (lane >> 3) & 1;
    const int l16 = (lane >> 4) & 1;

    load_chunk(0, 0);

    for (int t = 0; t < NCHUNK; t++) {
        CP_WAIT(0);
        __syncthreads();                 // publish load t; order prior reads
        if (t + 1 < NCHUNK) load_chunk(t + 1, (t + 1) & 1);

        const int s = t & 1;
        const uint32_t aHi = s0 + s * STAGE_B;
        const uint32_t aLo = aHi + TB;
        const uint32_t bHi = aHi + 2 * TB;
        const uint32_t bLo = aHi + 3 * TB;

        #pragma unroll
        for (int ks = 0; ks < 2; ks++) {
            const int kb = ks * 16;
            uint32_t bhif[4][2], blof[4][2];
            #pragma unroll
            for (int bp = 0; bp < 2; bp++) {
                uint32_t off = (uint32_t)((wn * 32 + bp * 16 + l16 * 8 + l7) * 80 +
                                          (kb + l8 * 8) * 2);
                uint32_t r0, r1, r2, r3;
                LDMATRIX_X4(r0, r1, r2, r3, bHi + off);
                bhif[bp * 2 + 0][0] = r0; bhif[bp * 2 + 0][1] = r1;
                bhif[bp * 2 + 1][0] = r2; bhif[bp * 2 + 1][1] = r3;
                LDMATRIX_X4(r0, r1, r2, r3, bLo + off);
                blof[bp * 2 + 0][0] = r0; blof[bp * 2 + 0][1] = r1;
                blof[bp * 2 + 1][0] = r2; blof[bp * 2 + 1][1] = r3;
            }
            #pragma unroll
            for (int mh = 0; mh < 2; mh++) {
                uint32_t afrag[2][4];
                // A-hi fragments
                #pragma unroll
                for (int mi = 0; mi < 2; mi++) {
                    int mt = mh * 2 + mi;
                    uint32_t addr = aHi +
                        (uint32_t)((wm * 64 + mt * 16 + l8 * 8 + l7) * 80 +
                                   (kb + l16 * 8) * 2);
                    LDMATRIX_X4(afrag[mi][0], afrag[mi][1], afrag[mi][2], afrag[mi][3], addr);
                }
                // pass 1: aHi * Bhi over all 8 accs (distance 8)
                #pragma unroll
                for (int mi = 0; mi < 2; mi++)
                    #pragma unroll
                    for (int nt = 0; nt < 4; nt++)
                        mma_bf16(acc[mh * 2 + mi][nt], afrag[mi], bhif[nt]);
                // pass 2: aHi * Blo over all 8 accs
                #pragma unroll
                for (int mi = 0; mi < 2; mi++)
                    #pragma unroll
                    for (int nt = 0; nt < 4; nt++)
                        mma_bf16(acc[mh * 2 + mi][nt], afrag[mi], blof[nt]);
                // A-lo fragments (reuse regs)
                #pragma unroll
                for (int mi = 0; mi < 2; mi++) {
                    int mt = mh * 2 + mi;
                    uint32_t addr = aLo +
                        (uint32_t)((wm * 64 + mt * 16 + l8 * 8 + l7) * 80 +
                                   (kb + l16 * 8) * 2);
                    LDMATRIX_X4(afrag[mi][0], afrag[mi][1], afrag[mi][2], afrag[mi][3], addr);
                }
                // pass 3: aLo * Bhi over all 8 accs
                #pragma unroll
                for (int mi = 0; mi < 2; mi++)
                    #pragma unroll
                    for (int nt = 0; nt < 4; nt++)
                        mma_bf16(acc[mh * 2 + mi][nt], afrag[mi], bhif[nt]);
            }
        }
    }

    // epilogue
    if (z == 2) {
        #pragma unroll
        for (int mt = 0; mt < 4; mt++) {
            #pragma unroll
            for (int half = 0; half < 2; half++) {
                int m = bm0 + wm * 64 + mt * 16 + grp + half * 8;
                int bb = m >> 11;
                int ss = m & (SEQ - 1);
                #pragma unroll
                for (int nt = 0; nt < 4; nt++) {
                    int n = bn0 + wn * 32 + nt * 8 + q4 * 2;
                    int h = n >> 6, d = n & 63;
                    size_t idx = (((size_t)(bb * NHEADS + h) * SEQ + ss) << 6) + d;
                    *(uint32_t*)&g_vh[idx] =
                        pack_h2(acc[mt][nt][half * 2 + 0], acc[mt][nt][half * 2 + 1]);
                }
            }
        }
    } else {
        __nv_bfloat16* dhi = (z == 0) ? g_qhi : g_khi;
        __nv_bfloat16* dlo = (z == 0) ? g_qlo : g_klo;
        #pragma unroll
        for (int mt = 0; mt < 4; mt++) {
            #pragma unroll
            for (int half = 0; half < 2; half++) {
                int m = bm0 + wm * 64 + mt * 16 + grp + half * 8;
                int bb = m >> 11;
                int ss = m & (SEQ - 1);
                #pragma unroll
                for (int nt = 0; nt < 4; nt++) {
                    int n = bn0 + wn * 32 + nt * 8 + q4 * 2;
                    int h = n >> 6, d = n & 63;
                    float x = acc[mt][nt][half * 2 + 0];
                    float y = acc[mt][nt][half * 2 + 1];
                    float xh = __bfloat162float(__float2bfloat16(x));
                    float yh = __bfloat162float(__float2bfloat16(y));
                    size_t idx = (((size_t)(bb * NHEADS + h) * SEQ + ss) << 6) + d;
                    *(uint32_t*)&dhi[idx] = pack_bf2(x, y);
                    *(uint32_t*)&dlo[idx] = pack_bf2(x - xh, y - yh);
                }
            }
        }
    }
}

// ---------------------------------------------------------------------------
// Kernel 4: flash attention. QK = 3-product bf16 split with REORDERED issue
// (all qhi*Khi over 8 accs, then qlo*Khi, then qhi*Klo -> distance 8);
// PV = single fp16 product (already distance 8).
// ---------------------------------------------------------------------------
#define AT_RB   144
#define AT_TILE (64 * AT_RB)                      // 9216 B per 64x64 tile
#define A2NS    2
#define A2_BW   (A2NS * 3 * AT_TILE)              // 55296
#define A2_MW   (A2_BW + A2NS * 128 * 4)          // 56320
#define A2_SMEM (A2_MW + A2NS * 64 * 4)           // 56832
#define NKT     (SEQ / 64)

__global__ void __launch_bounds__(128, 3) attn_mma_kernel(
    const float* __restrict__ key_mask, float* __restrict__ out)
{
    extern __shared__ char dsm[];
    const uint32_t sb = smem_u32(dsm);

    const int tid  = threadIdx.x;
    const int lane = tid & 31;
    const int wid  = tid >> 5;
    const int g    = lane >> 2;
    const int q4   = lane & 3;
    const int l7   = lane & 7;
    const int l8   = (lane >> 3) & 1;
    const int l16  = (lane >> 4) & 1;

    const int qt0 = blockIdx.x * 64;
    const int h   = blockIdx.y;
    const int b   = blockIdx.z;
    const size_t bh = ((size_t)(b * NHEADS + h)) << 17;

    const __nv_bfloat16* Khi = g_khi + bh;
    const __nv_bfloat16* Klo = g_klo + bh;
    const __nv_bfloat16* Vh  = (const __nv_bfloat16*)(g_vh + bh);  // addr only
    const float* bias_h = g_bias + h * 4096;

    auto issue_kv = [&](int kt, int s) {
        const __nv_bfloat16* srcs[3] = { Khi, Klo, Vh };
        #pragma unroll
        for (int arr = 0; arr < 3; arr++)
            #pragma unroll
            for (int jj = 0; jj < 4; jj++) {
                int rem = jj * 128 + tid;
                int row = rem >> 3, part = rem & 7;
                uint32_t dst = sb + (s * 3 + arr) * AT_TILE + row * AT_RB + part * 16;
                CP_ASYNC16(dst, srcs[arr] + (size_t)(kt * 64 + row) * HEAD + part * 8);
            }
        CP_COMMIT();
        float* bw = (float*)(dsm + A2_BW + s * 512);
        float* mw = (float*)(dsm + A2_MW + s * 256);
        if (tid < 127) {
            int idx = kt * 64 + tid - 63 - qt0 + 2047;
            idx = max(0, min(4094, idx));
            bw[tid] = bias_h[idx];
        }
        if (tid < 64) {
            float mk = key_mask[(size_t)b * SEQ + kt * 64 + tid];
            mw[tid] = (1.0f - mk) * -10000.0f;
        }
    };

    issue_kv(0, 0);

    // ---- Q fragments: direct gmem->register loads in mma A-layout ----
    uint32_t qhi[4][4], qlo[4][4];
    {
        const __nv_bfloat16* Qh = g_qhi + bh;
        const __nv_bfloat16* Ql = g_qlo + bh;
        int r0 = qt0 + wid * 16 + g;
        #pragma unroll
        for (int kk = 0; kk < 4; kk++) {
            int c0 = kk * 16 + q4 * 2;
            qhi[kk][0] = *(const uint32_t*)&Qh[(size_t)(r0)     * HEAD + c0];
            qhi[kk][1] = *(const uint32_t*)&Qh[(size_t)(r0 + 8) * HEAD + c0];
            qhi[kk][2] = *(const uint32_t*)&Qh[(size_t)(r0)     * HEAD + c0 + 8];
            qhi[kk][3] = *(const uint32_t*)&Qh[(size_t)(r0 + 8) * HEAD + c0 + 8];
            qlo[kk][0] = *(const uint32_t*)&Ql[(size_t)(r0)     * HEAD + c0];
            qlo[kk][1] = *(const uint32_t*)&Ql[(size_t)(r0 + 8) * HEAD + c0];
            qlo[kk][2] = *(const uint32_t*)&Ql[(size_t)(r0)     * HEAD + c0 + 8];
            qlo[kk][3] = *(const uint32_t*)&Ql[(size_t)(r0 + 8) * HEAD + c0 + 8];
        }
    }

    float oacc[8][4];
    #pragma unroll
    for (int nt = 0; nt < 8; nt++)
        #pragma unroll
        for (int r = 0; r < 4; r++) oacc[nt][r] = 0.0f;
    float mrow[2] = { -INFINITY, -INFINITY };
    float lrow[2] = { 0.0f, 0.0f };

    for (int t = 0; t < NKT; t++) {
        CP_WAIT(0);
        __syncthreads();                 // publish load t; order prior reads
        if (t + 1 < NKT) issue_kv(t + 1, (t + 1) & 1);

        const int s = t & 1;
        const uint32_t kb_hi = sb + (s * 3 + 0) * AT_TILE;
        const uint32_t kb_lo = sb + (s * 3 + 1) * AT_TILE;
        const uint32_t vb    = sb + (s * 3 + 2) * AT_TILE;
        const float* bw = (const float*)(dsm + A2_BW + s * 512);
        const float* mw = (const float*)(dsm + A2_MW + s * 256);

        // ---- S = Q K^T (3-pass bf16 split, distance-8 issue order) ----
        float sacc[8][4];
        #pragma unroll
        for (int nt = 0; nt < 8; nt++)
            #pragma unroll
            for (int r = 0; r < 4; r++) sacc[nt][r] = 0.0f;

        #pragma unroll
        for (int kk = 0; kk < 4; kk++) {
            uint32_t bhif[8][2], blof[8][2];
            #pragma unroll
            for (int bp = 0; bp < 4; bp++) {
                uint32_t off = (uint32_t)((bp * 16 + l16 * 8 + l7) * AT_RB +
                                          (kk * 16 + l8 * 8) * 2);
                uint32_t r0, r1, r2, r3;
                LDMATRIX_X4(r0, r1, r2, r3, kb_hi + off);
                bhif[bp * 2][0] = r0; bhif[bp * 2][1] = r1;
                bhif[bp * 2 + 1][0] = r2; bhif[bp * 2 + 1][1] = r3;
                LDMATRIX_X4(r0, r1, r2, r3, kb_lo + off);
                blof[bp * 2][0] = r0; blof[bp * 2][1] = r1;
                blof[bp * 2 + 1][0] = r2; blof[bp * 2 + 1][1] = r3;
            }
            #pragma unroll
            for (int nt = 0; nt < 8; nt++)
                mma_bf16(sacc[nt], qhi[kk], bhif[nt]);
            #pragma unroll
            for (int nt = 0; nt < 8; nt++)
                mma_bf16(sacc[nt], qlo[kk], bhif[nt]);
            #pragma unroll
            for (int nt = 0; nt < 8; nt++)
                mma_bf16(sacc[nt], qhi[kk], blof[nt]);
        }

        // ---- softmax in registers ----
        #pragma unroll
        for (int hl = 0; hl < 2; hl++) {
            int rr = wid * 16 + g + hl * 8;
            float mx = -INFINITY;
            #pragma unroll
            for (int nt = 0; nt < 8; nt++) {
                #pragma unroll
                for (int e = 0; e < 2; e++) {
                    int c = nt * 8 + q4 * 2 + e;
                    float v = sacc[nt][hl * 2 + e] + bw[c - rr + 63] + mw[c];
                    sacc[nt][hl * 2 + e] = v;
                    mx = fmaxf(mx, v);
                }
            }
            mx = fmaxf(mx, __shfl_xor_sync(0xffffffffu, mx, 1));
            mx = fmaxf(mx, __shfl_xor_sync(0xffffffffu, mx, 2));
            float mnew = fmaxf(mrow[hl], mx);
            float corr = __expf(mrow[hl] - mnew);
            mrow[hl] = mnew;
            float sum = 0.0f;
            #pragma unroll
            for (int nt = 0; nt < 8; nt++) {
                #pragma unroll
                for (int e = 0; e < 2; e++) {
                    float p = __expf(sacc[nt][hl * 2 + e] - mnew);
                    sacc[nt][hl * 2 + e] = p;
                    sum += p;
                }
            }
            sum += __shfl_xor_sync(0xffffffffu, sum, 1);
            sum += __shfl_xor_sync(0xffffffffu, sum, 2);
            lrow[hl] = lrow[hl] * corr + sum;
            #pragma unroll
            for (int nt = 0; nt < 8; nt++) {
                oacc[nt][hl * 2 + 0] *= corr;
                oacc[nt][hl * 2 + 1] *= corr;
            }
        }

        // ---- P -> fp16 A-fragments ----
        uint32_t ph[4][4];
        #pragma unroll
        for (int kk = 0; kk < 4; kk++) {
            #pragma unroll
            for (int part = 0; part < 4; part++) {
                int nt = 2 * kk + (part >> 1);
                int o = (part & 1) * 2;
                ph[kk][part] = pack_h2(sacc[nt][o], sacc[nt][o + 1]);
            }
        }

        // ---- O += P V (fp16 single product), V via trans ldmatrix ----
        #pragma unroll
        for (int kk = 0; kk < 4; kk++) {
            uint32_t vhf[8][2];
            #pragma unroll
            for (int db = 0; db < 4; db++) {
                uint32_t off = (uint32_t)((kk * 16 + l8 * 8 + l7) * AT_RB +
                                          (db * 16 + l16 * 8) * 2);
                uint32_t r0, r1, r2, r3;
                LDMATRIX_X4T(r0, r1, r2, r3, vb + off);
                vhf[db * 2][0] = r0; vhf[db * 2][1] = r1;
                vhf[db * 2 + 1][0] = r2; vhf[db * 2 + 1][1] = r3;
            }
            #pragma unroll
            for (int nt = 0; nt < 8; nt++)
                mma_fp16(oacc[nt], ph[kk], vhf[nt]);
        }
    }

    // ---- epilogue: out[b][qrow][h*64 + d] = O / l ----
    #pragma unroll
    for (int hl = 0; hl < 2; hl++) {
        int rr = wid * 16 + g + hl * 8;
        float inv = 1.0f / lrow[hl];
        size_t base = ((size_t)(b * SEQ + qt0 + rr)) * (NHEADS * HEAD) + h * HEAD;
        #pragma unroll
        for (int nt = 0; nt < 8; nt++) {
            int c = nt * 8 + q4 * 2;
            float2 v;
            v.x = oacc[nt][hl * 2 + 0] * inv;
            v.y = oacc[nt][hl * 2 + 1] * inv;
            *(float2*)&out[base + c] = v;
        }
    }
}

// ---------------------------------------------------------------------------
// Launch
// ---------------------------------------------------------------------------
extern "C" void kernel_launch(void* const* d_in, const int* in_sizes, int n_in,
                              void* d_out, int out_size) {
    const float* query    = (const float*)d_in[0];
    const float* key      = (const float*)d_in[1];
    const float* value    = (const float*)d_in[2];
    const float* key_mask = (const float*)d_in[3];
    const float* Wq       = (const float*)d_in[4];
    const float* Wk       = (const float*)d_in[5];
    const float* Wv       = (const float*)d_in[6];
    const float* bias_tab = (const float*)d_in[7];
    float* out = (float*)d_out;

    cudaFuncSetAttribute(proj_mma_kernel,
                         cudaFuncAttributeMaxDynamicSharedMemorySize, PROJ_SMEM);
    cudaFuncSetAttribute(attn_mma_kernel,
                         cudaFuncAttributeMaxDynamicSharedMemorySize, A2_SMEM);

    bias_precompute_kernel<<<16, 256>>>(bias_tab);
    convert_x_kernel<<<dim3(4096, 3), 256>>>(query, key, value);
    convert_w_kernel<<<dim3(32, 32, 3), dim3(32, 32)>>>(Wq, Wk, Wv);
    proj_mma_kernel<<<dim3(8, 32, 3), 256, PROJ_SMEM>>>();
    attn_mma_kernel<<<dim3(SEQ / 64, NHEADS, NB), 128, A2_SMEM>>>(key_mask, out);
}